// round 7
// baseline (speedup 1.0000x reference)
#include <cuda_runtime.h>
#include <mma.h>
#include <cstdint>

using namespace nvcuda;

#define Bdim 8
#define Hdim 16
#define Sdim 4096
#define Ddim 64
#define Kdim 256
#define BH (Bdim * Hdim)

// ---------------------------------------------------------------------------
// Scratch (static __device__; no allocation). tf32 hi/lo split operand arrays.
// ---------------------------------------------------------------------------
__device__ float g_qhi[(size_t)BH * Sdim * Ddim];          // [bh][s][d]
__device__ float g_qlo[(size_t)BH * Sdim * Ddim];
__device__ float g_kvhi[(size_t)2 * BH * Sdim * Ddim];     // [which][bh][n][d] (masked)
__device__ float g_kvlo[(size_t)2 * BH * Sdim * Ddim];
__device__ float g_phi[(size_t)2 * Sdim * Kdim];           // [which][n][kk]
__device__ float g_plo[(size_t)2 * Sdim * Kdim];
__device__ float g_kpT_hi[(size_t)BH * Ddim * Kdim];       // [bh][d][kk]
__device__ float g_kpT_lo[(size_t)BH * Ddim * Kdim];
__device__ float g_vp_hi[(size_t)BH * Kdim * Ddim];        // [bh][kk][d]
__device__ float g_vp_lo[(size_t)BH * Kdim * Ddim];

__device__ __forceinline__ void split1(float x, float& h, float& l) {
    h = wmma::__float_to_tf32(x);
    l = wmma::__float_to_tf32(x - h);
}

// ---------------------------------------------------------------------------
// Pre-pass: plain hi/lo split (q, proj_k, proj_v)
// ---------------------------------------------------------------------------
__global__ __launch_bounds__(256) void split_plain(
    const float* __restrict__ src, float* __restrict__ hi, float* __restrict__ lo,
    size_t n4)
{
    for (size_t i = (size_t)blockIdx.x * 256 + threadIdx.x; i < n4;
         i += (size_t)gridDim.x * 256) {
        float4 v = ((const float4*)src)[i];
        float4 h, l;
        split1(v.x, h.x, l.x); split1(v.y, h.y, l.y);
        split1(v.z, h.z, l.z); split1(v.w, h.w, l.w);
        ((float4*)hi)[i] = h;
        ((float4*)lo)[i] = l;
    }
}

// Pre-pass: k/v with mask applied, hi/lo split.
__global__ __launch_bounds__(256) void split_kv_kernel(
    const float* __restrict__ kin, const float* __restrict__ vin,
    const float* __restrict__ mask)
{
    const int which = blockIdx.y;
    const float* src = which ? vin : kin;
    float* hi = g_kvhi + (size_t)which * BH * Sdim * Ddim;
    float* lo = g_kvlo + (size_t)which * BH * Sdim * Ddim;
    const size_t n4 = (size_t)BH * Sdim * Ddim / 4;
    for (size_t i = (size_t)blockIdx.x * 256 + threadIdx.x; i < n4;
         i += (size_t)gridDim.x * 256) {
        float4 v = ((const float4*)src)[i];
        size_t e = i * 4;                               // bh*S*D + n*D + d
        size_t n = (e >> 6) & (Sdim - 1);
        size_t b = e / ((size_t)Hdim * Sdim * Ddim);
        float m = mask[b * Sdim + n];
        v.x *= m; v.y *= m; v.z *= m; v.w *= m;
        float4 h, l;
        split1(v.x, h.x, l.x); split1(v.y, h.y, l.y);
        split1(v.z, h.z, l.z); split1(v.w, h.w, l.w);
        ((float4*)hi)[i] = h;
        ((float4*)lo)[i] = l;
    }
}

// ---------------------------------------------------------------------------
// Stage A: per (bh, which): C[kk=256, d=64] = sum_n proj[n,kk] * kv[n,d]
// WMMA tf32 3x-split, all fragments loaded DIRECTLY from gmem (L2-resident
// panels) — no smem staging, no syncs in the mainloop.
// 256 threads / 8 warps: warp tile M=64 x N=32 (4mi x 2ni). K-step 8, 512 iters.
// ---------------------------------------------------------------------------
#define STG_LD 68
#define PROJ_SMEM ((size_t)256 * STG_LD * 4)   // 69.6 KB epilogue stage

__global__ __launch_bounds__(256) void kvproj_wmma_dg()
{
    extern __shared__ float sstage[];
    const int bh = blockIdx.x;
    const int which = blockIdx.y;
    const int t = threadIdx.x, wid = t >> 5;
    const int m0 = (wid & 3) * 64;
    const int n0 = (wid >> 2) * 32;

    const float* Ah = g_phi + (size_t)which * Sdim * Kdim;
    const float* Al = g_plo + (size_t)which * Sdim * Kdim;
    const float* Bh = g_kvhi + (size_t)(which * BH + bh) * Sdim * Ddim;
    const float* Bl = g_kvlo + (size_t)(which * BH + bh) * Sdim * Ddim;

    wmma::fragment<wmma::accumulator, 16, 16, 8, float> acc[4][2];
#pragma unroll
    for (int mi = 0; mi < 4; mi++)
#pragma unroll
        for (int ni = 0; ni < 2; ni++) wmma::fill_fragment(acc[mi][ni], 0.0f);

#pragma unroll 1
    for (int k0 = 0; k0 < Sdim; k0 += 8) {
        wmma::fragment<wmma::matrix_a, 16, 16, 8, wmma::precision::tf32,
                       wmma::col_major> ah[4], al[4];
        wmma::fragment<wmma::matrix_b, 16, 16, 8, wmma::precision::tf32,
                       wmma::row_major> bhf[2], blf[2];
#pragma unroll
        for (int mi = 0; mi < 4; mi++) {
            // A col_major: element (kk_r, n_c) at base[r + c*Kdim]
            wmma::load_matrix_sync(ah[mi], Ah + (size_t)k0 * Kdim + m0 + mi * 16, Kdim);
            wmma::load_matrix_sync(al[mi], Al + (size_t)k0 * Kdim + m0 + mi * 16, Kdim);
        }
#pragma unroll
        for (int ni = 0; ni < 2; ni++) {
            wmma::load_matrix_sync(bhf[ni], Bh + (size_t)k0 * Ddim + n0 + ni * 16, Ddim);
            wmma::load_matrix_sync(blf[ni], Bl + (size_t)k0 * Ddim + n0 + ni * 16, Ddim);
        }
#pragma unroll
        for (int mi = 0; mi < 4; mi++)
#pragma unroll
            for (int ni = 0; ni < 2; ni++) {
                wmma::mma_sync(acc[mi][ni], ah[mi], blf[ni], acc[mi][ni]);
                wmma::mma_sync(acc[mi][ni], al[mi], bhf[ni], acc[mi][ni]);
                wmma::mma_sync(acc[mi][ni], ah[mi], bhf[ni], acc[mi][ni]);
            }
    }

    // ---- epilogue: stage C [256 x 64] in smem, split + layout-specific write
#pragma unroll
    for (int mi = 0; mi < 4; mi++)
#pragma unroll
        for (int ni = 0; ni < 2; ni++)
            wmma::store_matrix_sync(sstage + (size_t)(m0 + mi * 16) * STG_LD + n0 + ni * 16,
                                    acc[mi][ni], STG_LD, wmma::mem_row_major);
    __syncthreads();

    if (which == 0) {
        float* dh = g_kpT_hi + (size_t)bh * Ddim * Kdim;    // [d][kk]
        float* dl = g_kpT_lo + (size_t)bh * Ddim * Kdim;
#pragma unroll
        for (int l = 0; l < 16; l++) {
            int v4i = t + l * 256;
            int d = v4i >> 6, kq = v4i & 63;
            float4 h, lo;
#pragma unroll
            for (int j = 0; j < 4; j++) {
                float val = sstage[(size_t)(kq * 4 + j) * STG_LD + d];
                split1(val, (&h.x)[j], (&lo.x)[j]);
            }
            *(float4*)&dh[(size_t)d * Kdim + kq * 4] = h;
            *(float4*)&dl[(size_t)d * Kdim + kq * 4] = lo;
        }
    } else {
        float* dh = g_vp_hi + (size_t)bh * Kdim * Ddim;     // [kk][d]
        float* dl = g_vp_lo + (size_t)bh * Kdim * Ddim;
#pragma unroll
        for (int l = 0; l < 16; l++) {
            int v4i = t + l * 256;
            int kk = v4i >> 4, d4 = v4i & 15;
            float4 h, lo;
#pragma unroll
            for (int j = 0; j < 4; j++) {
                float val = sstage[(size_t)kk * STG_LD + d4 * 4 + j];
                split1(val, (&h.x)[j], (&lo.x)[j]);
            }
            *(float4*)&dh[(size_t)kk * Ddim + d4 * 4] = h;
            *(float4*)&dl[(size_t)kk * Ddim + d4 * 4] = lo;
        }
    }
}

// ---------------------------------------------------------------------------
// Attn: per (bh, 64-q tile), 256 threads / 8 warps.
//  P1: S[64,256] = Q[64,64] @ KT[64,256]   (WMMA 3xtf32, gmem frags) -> smem
//  P2: fp32 softmax (4 lanes/row), write p_hi -> sc, p_lo -> plo
//  P2b: probs = hi+lo coalesced gmem write
//  P3: O[64,64] = P[64,256] @ V[256,64]    (WMMA 3xtf32; A from smem, B gmem)
// ---------------------------------------------------------------------------
#define SC_LD 264
#define ATTN_SMEM ((size_t)2 * 64 * SC_LD * 4)   // 135.2 KB

__global__ __launch_bounds__(256) void attn_wmma(
    float* __restrict__ out, float* __restrict__ probs)
{
    extern __shared__ float sm[];
    float* sc  = sm;                 // 64 x SC_LD : scores -> p_hi
    float* plo = sm + 64 * SC_LD;    // 64 x SC_LD : p_lo

    const int bh = blockIdx.y;
    const int q0 = blockIdx.x * 64;
    const int t = threadIdx.x, wid = t >> 5;

    // ---- P1: scores ----
    {
        const int n0 = wid * 32;     // each warp: full M=64, N=32 slice
        wmma::fragment<wmma::accumulator, 16, 16, 8, float> acc[4][2];
#pragma unroll
        for (int mi = 0; mi < 4; mi++)
#pragma unroll
            for (int ni = 0; ni < 2; ni++) wmma::fill_fragment(acc[mi][ni], 0.0f);

        const float* qh = g_qhi + ((size_t)bh * Sdim + q0) * Ddim;
        const float* ql = g_qlo + ((size_t)bh * Sdim + q0) * Ddim;
        const float* kh = g_kpT_hi + (size_t)bh * Ddim * Kdim;
        const float* kl = g_kpT_lo + (size_t)bh * Ddim * Kdim;

#pragma unroll
        for (int ks = 0; ks < 8; ks++) {
            const int d0 = ks * 8;
            wmma::fragment<wmma::matrix_a, 16, 16, 8, wmma::precision::tf32,
                           wmma::row_major> ah[4], al[4];
            wmma::fragment<wmma::matrix_b, 16, 16, 8, wmma::precision::tf32,
                           wmma::row_major> bhf[2], blf[2];
#pragma unroll
            for (int mi = 0; mi < 4; mi++) {
                wmma::load_matrix_sync(ah[mi], qh + (size_t)(mi * 16) * Ddim + d0, Ddim);
                wmma::load_matrix_sync(al[mi], ql + (size_t)(mi * 16) * Ddim + d0, Ddim);
            }
#pragma unroll
            for (int ni = 0; ni < 2; ni++) {
                wmma::load_matrix_sync(bhf[ni], kh + (size_t)d0 * Kdim + n0 + ni * 16, Kdim);
                wmma::load_matrix_sync(blf[ni], kl + (size_t)d0 * Kdim + n0 + ni * 16, Kdim);
            }
#pragma unroll
            for (int mi = 0; mi < 4; mi++)
#pragma unroll
                for (int ni = 0; ni < 2; ni++) {
                    wmma::mma_sync(acc[mi][ni], ah[mi], blf[ni], acc[mi][ni]);
                    wmma::mma_sync(acc[mi][ni], al[mi], bhf[ni], acc[mi][ni]);
                    wmma::mma_sync(acc[mi][ni], ah[mi], bhf[ni], acc[mi][ni]);
                }
        }
#pragma unroll
        for (int mi = 0; mi < 4; mi++)
#pragma unroll
            for (int ni = 0; ni < 2; ni++) {
#pragma unroll
                for (int e = 0; e < acc[mi][ni].num_elements; e++)
                    acc[mi][ni].x[e] *= 0.125f;
                wmma::store_matrix_sync(sc + (size_t)(mi * 16) * SC_LD + n0 + ni * 16,
                                        acc[mi][ni], SC_LD, wmma::mem_row_major);
            }
    }
    __syncthreads();

    // ---- P2: softmax (row = t>>2, 4 lanes x 64 values) ----
    {
        const int row = t >> 2;
        const int seg = t & 3;
        float* base  = sc  + row * SC_LD + seg * 64;
        float* baseL = plo + row * SC_LD + seg * 64;
        float v[64];
#pragma unroll
        for (int i = 0; i < 16; i++) {
            float4 f = *(float4*)&base[i * 4];
            v[i * 4] = f.x; v[i * 4 + 1] = f.y; v[i * 4 + 2] = f.z; v[i * 4 + 3] = f.w;
        }
        float mx = -1e30f;
#pragma unroll
        for (int i = 0; i < 64; i++) mx = fmaxf(mx, v[i]);
        mx = fmaxf(mx, __shfl_xor_sync(0xffffffffu, mx, 1));
        mx = fmaxf(mx, __shfl_xor_sync(0xffffffffu, mx, 2));
        float sum = 0.0f;
#pragma unroll
        for (int i = 0; i < 64; i++) { v[i] = __expf(v[i] - mx); sum += v[i]; }
        sum += __shfl_xor_sync(0xffffffffu, sum, 1);
        sum += __shfl_xor_sync(0xffffffffu, sum, 2);
        float inv = __fdividef(1.0f, sum);
#pragma unroll
        for (int i = 0; i < 16; i++) {
            float4 h, l;
#pragma unroll
            for (int j = 0; j < 4; j++)
                split1(v[i * 4 + j] * inv, (&h.x)[j], (&l.x)[j]);
            *(float4*)&base[i * 4]  = h;
            *(float4*)&baseL[i * 4] = l;
        }
    }
    __syncthreads();

    // ---- P2b: probs write (hi+lo, exact to ~2.4e-7; fully coalesced) ----
    if (probs) {
        float* pb = probs + ((size_t)bh * Sdim + q0) * Kdim;
#pragma unroll
        for (int l = 0; l < 16; l++) {
            int v4i = t + l * 256;               // 4096 float4 = 64 x 256
            int row = v4i >> 6, c4 = v4i & 63;
            float4 h = *(const float4*)&sc[row * SC_LD + c4 * 4];
            float4 lo = *(const float4*)&plo[row * SC_LD + c4 * 4];
            *(float4*)&pb[(size_t)row * Kdim + c4 * 4] =
                make_float4(h.x + lo.x, h.y + lo.y, h.z + lo.z, h.w + lo.w);
        }
    }

    // ---- P3: out = P @ v_proj ----
    {
        const int m0 = (wid & 3) * 16;
        const int n0 = (wid >> 2) * 32;
        wmma::fragment<wmma::accumulator, 16, 16, 8, float> oacc[2];
#pragma unroll
        for (int ni = 0; ni < 2; ni++) wmma::fill_fragment(oacc[ni], 0.0f);

        const float* vh = g_vp_hi + (size_t)bh * Kdim * Ddim;
        const float* vl = g_vp_lo + (size_t)bh * Kdim * Ddim;

#pragma unroll 4
        for (int ks = 0; ks < 32; ks++) {
            const int k0 = ks * 8;
            wmma::fragment<wmma::matrix_a, 16, 16, 8, wmma::precision::tf32,
                           wmma::row_major> ah, al;
            wmma::fragment<wmma::matrix_b, 16, 16, 8, wmma::precision::tf32,
                           wmma::row_major> bhf[2], blf[2];
            wmma::load_matrix_sync(ah, sc  + (size_t)m0 * SC_LD + k0, SC_LD);
            wmma::load_matrix_sync(al, plo + (size_t)m0 * SC_LD + k0, SC_LD);
#pragma unroll
            for (int ni = 0; ni < 2; ni++) {
                wmma::load_matrix_sync(bhf[ni], vh + (size_t)k0 * Ddim + n0 + ni * 16, Ddim);
                wmma::load_matrix_sync(blf[ni], vl + (size_t)k0 * Ddim + n0 + ni * 16, Ddim);
            }
#pragma unroll
            for (int ni = 0; ni < 2; ni++) {
                wmma::mma_sync(oacc[ni], ah, blf[ni], oacc[ni]);
                wmma::mma_sync(oacc[ni], al, bhf[ni], oacc[ni]);
                wmma::mma_sync(oacc[ni], ah, bhf[ni], oacc[ni]);
            }
        }
        float* ob = out + ((size_t)bh * Sdim + q0 + m0) * Ddim;
#pragma unroll
        for (int ni = 0; ni < 2; ni++)
            wmma::store_matrix_sync(ob + n0 + ni * 16, oacc[ni], Ddim,
                                    wmma::mem_row_major);
    }
}

// ---------------------------------------------------------------------------
extern "C" void kernel_launch(void* const* d_in, const int* in_sizes, int n_in,
                              void* d_out, int out_size)
{
    const float* q    = (const float*)d_in[0];
    const float* k    = (const float*)d_in[1];
    const float* v    = (const float*)d_in[2];
    const float* mask = (const float*)d_in[3];
    const float* pk   = (const float*)d_in[4];
    const float* pv   = (const float*)d_in[5];

    float* out = (float*)d_out;
    const long OUT_ELEMS = (long)BH * Sdim * Ddim;   // 33,554,432
    float* probs = ((long)out_size > OUT_ELEMS) ? (out + OUT_ELEMS) : nullptr;

    cudaFuncSetAttribute(kvproj_wmma_dg, cudaFuncAttributeMaxDynamicSharedMemorySize,
                         (int)PROJ_SMEM);
    cudaFuncSetAttribute(attn_wmma, cudaFuncAttributeMaxDynamicSharedMemorySize,
                         (int)ATTN_SMEM);

    float *qhi, *qlo, *phiK, *ploK, *phiV, *ploV;
    cudaGetSymbolAddress((void**)&qhi, g_qhi);
    cudaGetSymbolAddress((void**)&qlo, g_qlo);
    cudaGetSymbolAddress((void**)&phiK, g_phi);
    cudaGetSymbolAddress((void**)&ploK, g_plo);
    phiV = phiK + (size_t)Sdim * Kdim;
    ploV = ploK + (size_t)Sdim * Kdim;

    const size_t qn4 = (size_t)BH * Sdim * Ddim / 4;
    const size_t pn4 = (size_t)Sdim * Kdim / 4;

    split_plain<<<8192, 256>>>(q, qhi, qlo, qn4);
    split_plain<<<1024, 256>>>(pk, phiK, ploK, pn4);
    split_plain<<<1024, 256>>>(pv, phiV, ploV, pn4);
    split_kv_kernel<<<dim3(8192, 2), 256>>>(k, v, mask);

    kvproj_wmma_dg<<<dim3(BH, 2), 256, PROJ_SMEM>>>();
    attn_wmma<<<dim3(Sdim / 64, BH), 256, ATTN_SMEM>>>(out, probs);
}

// round 11
// speedup vs baseline: 1.2961x; 1.2961x over previous
#include <cuda_runtime.h>
#include <mma.h>
#include <cstdint>

using namespace nvcuda;

#define Bdim 8
#define Hdim 16
#define Sdim 4096
#define Ddim 64
#define Kdim 256
#define BH (Bdim * Hdim)

// Scratch (fp32): projected K transposed [bh][d][kk], projected V [bh][kk][d].
__device__ float g_kprojT[(size_t)BH * Ddim * Kdim];
__device__ float g_vproj[(size_t)BH * Kdim * Ddim];

// ---------------------------------------------------------------------------
// helpers
// ---------------------------------------------------------------------------
__device__ __forceinline__ uint32_t smem_u32(const void* p) {
    uint32_t a;
    asm("{ .reg .u64 t; cvta.to.shared.u64 t, %1; cvt.u32.u64 %0, t; }"
        : "=r"(a) : "l"(p));
    return a;
}
__device__ __forceinline__ void cpa16(uint32_t dst, const void* src) {
    asm volatile("cp.async.cg.shared.global [%0], [%1], 16;" :: "r"(dst), "l"(src));
}
#define CPA_COMMIT() asm volatile("cp.async.commit_group;" ::: "memory")
#define CPA_WAIT0()  asm volatile("cp.async.wait_group 0;" ::: "memory")
#define CPA_WAIT1()  asm volatile("cp.async.wait_group 1;" ::: "memory")

// Split an fp32 fragment into tf32 hi/lo fragments (in registers).
template <typename FragT>
__device__ __forceinline__ void split_frag(const FragT& f, FragT& h, FragT& l) {
#pragma unroll
    for (int e = 0; e < f.num_elements; e++) {
        float hi = wmma::__float_to_tf32(f.x[e]);
        h.x[e] = hi;
        l.x[e] = wmma::__float_to_tf32(f.x[e] - hi);
    }
}

// ---------------------------------------------------------------------------
// Stage A: per (bh, which): C[kk=256, d=64] = sum_n proj[n,kk] * (kv[n,d]*m[n])
// 3x-tf32 WMMA (hi/lo split in registers). A staged via cp.async double-buffer;
// B via masked LDG->STS double-buffer. 256 threads / 8 warps; warp tile
// 64(kk) x 32(d). One __syncthreads per 32-deep K chunk.
// ---------------------------------------------------------------------------
#define PCH 32
#define PA_LD 260
#define PB_LD 68
#define PROJ_A_BYTES (PCH * PA_LD * 4)                 // 33280
#define PROJ_B_BYTES (PCH * PB_LD * 4)                 // 8704
#define PROJ_SMEM (2 * PROJ_A_BYTES + 2 * PROJ_B_BYTES) // 83968 (>= 256*68*4 epilogue)
#define NCH (Sdim / PCH)                               // 128

__global__ __launch_bounds__(256) void proj_gemm(
    const float* __restrict__ kin, const float* __restrict__ vin,
    const float* __restrict__ pk, const float* __restrict__ pv,
    const float* __restrict__ mask)
{
    extern __shared__ char smraw[];
    float* Abuf[2] = { (float*)smraw, (float*)(smraw + PROJ_A_BYTES) };
    float* Bbuf[2] = { (float*)(smraw + 2 * PROJ_A_BYTES),
                       (float*)(smraw + 2 * PROJ_A_BYTES + PROJ_B_BYTES) };
    const uint32_t sb = smem_u32(smraw);

    const int bh = blockIdx.x, which = blockIdx.y, b = bh >> 4;
    const int t = threadIdx.x, wid = t >> 5;
    const int m0 = (wid & 3) * 64;       // kk offset of warp
    const int n0c = (wid >> 2) * 32;     // d offset of warp

    const float* Ag = which ? pv : pk;                                // [S][256]
    const float* Bg = (which ? vin : kin) + (size_t)bh * Sdim * Ddim; // [S][64]
    const float* mk = mask + (size_t)b * Sdim;

    wmma::fragment<wmma::accumulator, 16, 16, 8, float> acc[4][2];
#pragma unroll
    for (int mi = 0; mi < 4; mi++)
#pragma unroll
        for (int ni = 0; ni < 2; ni++) wmma::fill_fragment(acc[mi][ni], 0.0f);

    float4 br[2];
    float brm[2];

    // ---- loaders ----
    auto cpaA = [&](int ch, int buf) {
        const uint32_t dst0 = sb + buf * PROJ_A_BYTES;
        const char* src = (const char*)(Ag + (size_t)ch * PCH * Kdim);
#pragma unroll
        for (int l = 0; l < 8; l++) {            // 2048 16B chunks / 256 thr
            int c = t + l * 256;
            int row = c >> 6, off = c & 63;      // 64 chunks per 1024B row
            cpa16(dst0 + row * (PA_LD * 4) + off * 16, src + row * 1024 + off * 16);
        }
    };
    auto ldgB = [&](int ch) {
#pragma unroll
        for (int l = 0; l < 2; l++) {
            int idx = t + l * 256;
            int row = idx >> 4, c4 = idx & 15;
            br[l]  = *(const float4*)&Bg[(size_t)(ch * PCH + row) * Ddim + c4 * 4];
            brm[l] = mk[ch * PCH + row];
        }
    };
    auto stsB = [&](int buf) {
#pragma unroll
        for (int l = 0; l < 2; l++) {
            int idx = t + l * 256;
            int row = idx >> 4, c4 = idx & 15;
            float4 v = br[l]; float m = brm[l];
            *(float4*)&Bbuf[buf][row * PB_LD + c4 * 4] =
                make_float4(v.x * m, v.y * m, v.z * m, v.w * m);
        }
    };
    auto do_mma = [&](int buf) {
        const float* A = Abuf[buf];
        const float* B = Bbuf[buf];
#pragma unroll
        for (int ks = 0; ks < 4; ks++) {
            wmma::fragment<wmma::matrix_b, 16, 16, 8, wmma::precision::tf32,
                           wmma::row_major> bf, bhh[2], bll[2];
#pragma unroll
            for (int ni = 0; ni < 2; ni++) {
                wmma::load_matrix_sync(bf, B + (ks * 8) * PB_LD + n0c + ni * 16, PB_LD);
                split_frag(bf, bhh[ni], bll[ni]);
            }
#pragma unroll
            for (int mi = 0; mi < 4; mi++) {
                wmma::fragment<wmma::matrix_a, 16, 16, 8, wmma::precision::tf32,
                               wmma::col_major> af, ah, al;
                wmma::load_matrix_sync(af, A + (ks * 8) * PA_LD + m0 + mi * 16, PA_LD);
                split_frag(af, ah, al);
#pragma unroll
                for (int ni = 0; ni < 2; ni++) {
                    wmma::mma_sync(acc[mi][ni], ah, bll[ni], acc[mi][ni]);
                    wmma::mma_sync(acc[mi][ni], al, bhh[ni], acc[mi][ni]);
                    wmma::mma_sync(acc[mi][ni], ah, bhh[ni], acc[mi][ni]);
                }
            }
        }
    };

    // ---- prologue ----
    ldgB(0);
    cpaA(0, 0);
    CPA_COMMIT();
    CPA_WAIT0();
    stsB(0);
    ldgB(1);
    __syncthreads();

    // ---- mainloop: one sync per chunk ----
    for (int i = 0; i < NCH; i++) {
        const int cur = i & 1, nxt = cur ^ 1;
        if (i + 1 < NCH) {
            cpaA(i + 1, nxt);
            CPA_COMMIT();
            stsB(nxt);                    // br holds chunk i+1
        }
        if (i + 2 < NCH) ldgB(i + 2);
        do_mma(cur);
        if (i + 1 < NCH) CPA_WAIT0();
        __syncthreads();
    }

    // ---- epilogue: stage [256kk][68] fp32, then layout-specific write ----
    float* stage = (float*)smraw;
#pragma unroll
    for (int mi = 0; mi < 4; mi++)
#pragma unroll
        for (int ni = 0; ni < 2; ni++)
            wmma::store_matrix_sync(stage + (size_t)(m0 + mi * 16) * 68 + n0c + ni * 16,
                                    acc[mi][ni], 68, wmma::mem_row_major);
    __syncthreads();

    if (which == 0) {
        float* dst = g_kprojT + (size_t)bh * Ddim * Kdim;   // [d][kk]
#pragma unroll
        for (int l = 0; l < 16; l++) {
            int v4i = t + l * 256;
            int d = v4i >> 6, kq = v4i & 63;
            float4 o;
            o.x = stage[(size_t)(kq * 4 + 0) * 68 + d];
            o.y = stage[(size_t)(kq * 4 + 1) * 68 + d];
            o.z = stage[(size_t)(kq * 4 + 2) * 68 + d];
            o.w = stage[(size_t)(kq * 4 + 3) * 68 + d];
            *(float4*)&dst[(size_t)d * Kdim + kq * 4] = o;
        }
    } else {
        float* dst = g_vproj + (size_t)bh * Kdim * Ddim;    // [kk][d]
#pragma unroll
        for (int l = 0; l < 16; l++) {
            int v4i = t + l * 256;
            int kk = v4i >> 4, d4 = v4i & 15;
            *(float4*)&dst[(size_t)kk * Ddim + d4 * 4] =
                *(const float4*)&stage[(size_t)kk * 68 + d4 * 4];
        }
    }
}

// ---------------------------------------------------------------------------
// Stage B: per (bh, 64-q tile), 256 threads / 8 warps.
//  cp.async: {q, kprojT} group0, vproj group1 (waited only before out-GEMM).
//  P1 scores = Q @ KT (3x-tf32 wmma) * 0.125 -> Sc
//  P2 fp32 softmax, probs written into P buffer (reuses KT region)
//  P3 probs -> gmem;  out = P @ Vproj (3x-tf32 wmma) -> gmem
// ---------------------------------------------------------------------------
#define AQ_LD 68
#define AK_LD 260
#define ASC_LD 260
#define AV_LD 68
#define OFF_Q 0
#define OFF_K  (64 * AQ_LD * 4)                      // 17408
#define OFF_SC (OFF_K + 64 * AK_LD * 4)              // 83968
#define OFF_V  (OFF_SC + 64 * ASC_LD * 4)            // 150528
#define ATTN_SMEM (OFF_V + 256 * AV_LD * 4)          // 220160

__global__ __launch_bounds__(256) void attn_wmma(
    const float* __restrict__ q, float* __restrict__ out, float* __restrict__ probs)
{
    extern __shared__ char smraw[];
    const uint32_t sb = smem_u32(smraw);
    float* Qs = (float*)(smraw + OFF_Q);     // [64][68]
    float* Ks = (float*)(smraw + OFF_K);     // [64][260]  (reused as P)
    float* Sc = (float*)(smraw + OFF_SC);    // [64][260]
    float* Vs = (float*)(smraw + OFF_V);     // [256][68]

    const int bh = blockIdx.y;
    const int q0 = blockIdx.x * 64;
    const int t = threadIdx.x, wid = t >> 5;

    // ---- async staging ----
    {
        const char* qg = (const char*)(q + ((size_t)bh * Sdim + q0) * Ddim);
#pragma unroll
        for (int l = 0; l < 4; l++) {            // q: 1024 chunks (64 rows x 16)
            int c = t + l * 256;
            int row = c >> 4, off = c & 15;
            cpa16(sb + OFF_Q + row * (AQ_LD * 4) + off * 16, qg + row * 256 + off * 16);
        }
        const char* kg = (const char*)(g_kprojT + (size_t)bh * Ddim * Kdim);
#pragma unroll
        for (int l = 0; l < 16; l++) {           // kT: 4096 chunks (64 rows x 64)
            int c = t + l * 256;
            int row = c >> 6, off = c & 63;
            cpa16(sb + OFF_K + row * (AK_LD * 4) + off * 16, kg + row * 1024 + off * 16);
        }
        CPA_COMMIT();                            // group 0: q + kT
        const char* vg = (const char*)(g_vproj + (size_t)bh * Kdim * Ddim);
#pragma unroll
        for (int l = 0; l < 16; l++) {           // vp: 4096 chunks (256 rows x 16)
            int c = t + l * 256;
            int row = c >> 4, off = c & 15;
            cpa16(sb + OFF_V + row * (AV_LD * 4) + off * 16, vg + row * 256 + off * 16);
        }
        CPA_COMMIT();                            // group 1: vp
    }
    CPA_WAIT1();                                 // q + kT ready
    __syncthreads();

    // ---- P1: scores (3x-tf32) ----
    {
        const int n0 = wid * 32;
        wmma::fragment<wmma::accumulator, 16, 16, 8, float> acc[4][2];
#pragma unroll
        for (int mi = 0; mi < 4; mi++)
#pragma unroll
            for (int ni = 0; ni < 2; ni++) wmma::fill_fragment(acc[mi][ni], 0.0f);

#pragma unroll
        for (int ks = 0; ks < 8; ks++) {
            const int d0 = ks * 8;
            wmma::fragment<wmma::matrix_b, 16, 16, 8, wmma::precision::tf32,
                           wmma::row_major> bf, bhh[2], bll[2];
#pragma unroll
            for (int ni = 0; ni < 2; ni++) {
                wmma::load_matrix_sync(bf, Ks + d0 * AK_LD + n0 + ni * 16, AK_LD);
                split_frag(bf, bhh[ni], bll[ni]);
            }
#pragma unroll
            for (int mi = 0; mi < 4; mi++) {
                wmma::fragment<wmma::matrix_a, 16, 16, 8, wmma::precision::tf32,
                               wmma::row_major> af, ah, al;
                wmma::load_matrix_sync(af, Qs + (mi * 16) * AQ_LD + d0, AQ_LD);
                split_frag(af, ah, al);
#pragma unroll
                for (int ni = 0; ni < 2; ni++) {
                    wmma::mma_sync(acc[mi][ni], ah, bll[ni], acc[mi][ni]);
                    wmma::mma_sync(acc[mi][ni], al, bhh[ni], acc[mi][ni]);
                    wmma::mma_sync(acc[mi][ni], ah, bhh[ni], acc[mi][ni]);
                }
            }
        }
#pragma unroll
        for (int mi = 0; mi < 4; mi++)
#pragma unroll
            for (int ni = 0; ni < 2; ni++) {
#pragma unroll
                for (int e = 0; e < acc[mi][ni].num_elements; e++)
                    acc[mi][ni].x[e] *= 0.125f;
                wmma::store_matrix_sync(Sc + (mi * 16) * ASC_LD + n0 + ni * 16,
                                        acc[mi][ni], ASC_LD, wmma::mem_row_major);
            }
    }
    __syncthreads();

    // ---- P2: softmax (64 rows x 4 lanes; lane handles cols (seg+4j)*4) ----
    {
        const int row = t >> 2;
        const int seg = t & 3;
        float v[64];
#pragma unroll
        for (int j = 0; j < 16; j++) {
            float4 f = *(const float4*)&Sc[row * ASC_LD + (seg + 4 * j) * 4];
            v[j * 4] = f.x; v[j * 4 + 1] = f.y; v[j * 4 + 2] = f.z; v[j * 4 + 3] = f.w;
        }
        float mx = -1e30f;
#pragma unroll
        for (int i = 0; i < 64; i++) mx = fmaxf(mx, v[i]);
        mx = fmaxf(mx, __shfl_xor_sync(0xffffffffu, mx, 1));
        mx = fmaxf(mx, __shfl_xor_sync(0xffffffffu, mx, 2));
        float sum = 0.0f;
#pragma unroll
        for (int i = 0; i < 64; i++) { v[i] = __expf(v[i] - mx); sum += v[i]; }
        sum += __shfl_xor_sync(0xffffffffu, sum, 1);
        sum += __shfl_xor_sync(0xffffffffu, sum, 2);
        float inv = __fdividef(1.0f, sum);
#pragma unroll
        for (int j = 0; j < 16; j++) {
            *(float4*)&Ks[row * AK_LD + (seg + 4 * j) * 4] =    // P buffer
                make_float4(v[j * 4] * inv, v[j * 4 + 1] * inv,
                            v[j * 4 + 2] * inv, v[j * 4 + 3] * inv);
        }
    }
    CPA_WAIT0();                                 // vp ready
    __syncthreads();

    // ---- P3a: probs -> gmem (from P buffer, coalesced) ----
    if (probs) {
        float* pb = probs + ((size_t)bh * Sdim + q0) * Kdim;
#pragma unroll
        for (int l = 0; l < 16; l++) {
            int v4i = t + l * 256;               // 4096 float4 = 64 x 256
            int row = v4i >> 6, c4 = v4i & 63;
            *(float4*)&pb[(size_t)row * Kdim + c4 * 4] =
                *(const float4*)&Ks[row * AK_LD + c4 * 4];
        }
    }

    // ---- P3b: out = P @ Vproj (3x-tf32) ----
    {
        const int m0 = (wid & 3) * 16;
        const int n0 = (wid >> 2) * 32;
        wmma::fragment<wmma::accumulator, 16, 16, 8, float> oacc[2];
#pragma unroll
        for (int ni = 0; ni < 2; ni++) wmma::fill_fragment(oacc[ni], 0.0f);

#pragma unroll 4
        for (int ks = 0; ks < 32; ks++) {
            const int k0 = ks * 8;
            wmma::fragment<wmma::matrix_a, 16, 16, 8, wmma::precision::tf32,
                           wmma::row_major> af, ah, al;
            wmma::fragment<wmma::matrix_b, 16, 16, 8, wmma::precision::tf32,
                           wmma::row_major> bf, bhh[2], bll[2];
            wmma::load_matrix_sync(af, Ks + m0 * AK_LD + k0, AK_LD);
            split_frag(af, ah, al);
#pragma unroll
            for (int ni = 0; ni < 2; ni++) {
                wmma::load_matrix_sync(bf, Vs + k0 * AV_LD + n0 + ni * 16, AV_LD);
                split_frag(bf, bhh[ni], bll[ni]);
            }
#pragma unroll
            for (int ni = 0; ni < 2; ni++) {
                wmma::mma_sync(oacc[ni], ah, bll[ni], oacc[ni]);
                wmma::mma_sync(oacc[ni], al, bhh[ni], oacc[ni]);
                wmma::mma_sync(oacc[ni], ah, bhh[ni], oacc[ni]);
            }
        }
        float* ob = out + ((size_t)bh * Sdim + q0 + m0) * Ddim;
#pragma unroll
        for (int ni = 0; ni < 2; ni++)
            wmma::store_matrix_sync(ob + n0 + ni * 16, oacc[ni], Ddim,
                                    wmma::mem_row_major);
    }
}

// ---------------------------------------------------------------------------
extern "C" void kernel_launch(void* const* d_in, const int* in_sizes, int n_in,
                              void* d_out, int out_size)
{
    const float* q    = (const float*)d_in[0];
    const float* k    = (const float*)d_in[1];
    const float* v    = (const float*)d_in[2];
    const float* mask = (const float*)d_in[3];
    const float* pk   = (const float*)d_in[4];
    const float* pv   = (const float*)d_in[5];

    float* out = (float*)d_out;
    const long OUT_ELEMS = (long)BH * Sdim * Ddim;   // 33,554,432
    float* probs = ((long)out_size > OUT_ELEMS) ? (out + OUT_ELEMS) : nullptr;

    cudaFuncSetAttribute(proj_gemm, cudaFuncAttributeMaxDynamicSharedMemorySize,
                         PROJ_SMEM);
    cudaFuncSetAttribute(attn_wmma, cudaFuncAttributeMaxDynamicSharedMemorySize,
                         ATTN_SMEM);

    proj_gemm<<<dim3(BH, 2), 256, PROJ_SMEM>>>(k, v, pk, pv, mask);
    attn_wmma<<<dim3(Sdim / 64, BH), 256, ATTN_SMEM>>>(q, out, probs);
}

// round 12
// speedup vs baseline: 2.2769x; 1.7567x over previous
#include <cuda_runtime.h>
#include <mma.h>
#include <cuda_bf16.h>
#include <cstdint>

using namespace nvcuda;

#define Bdim 8
#define Hdim 16
#define Sdim 4096
#define Ddim 64
#define Kdim 256
#define BH (Bdim * Hdim)

typedef __nv_bfloat16 bf16;

// ---------------------------------------------------------------------------
// Scratch: bf16 hi/lo split operand arrays (no allocation; __device__ globals)
// ---------------------------------------------------------------------------
__device__ bf16 g_q_hi[(size_t)BH * Sdim * Ddim];      // [bh][s][d]
__device__ bf16 g_q_lo[(size_t)BH * Sdim * Ddim];
__device__ bf16 g_kv_hi[(size_t)2 * BH * Sdim * Ddim]; // [which][bh][n][d] masked
__device__ bf16 g_kv_lo[(size_t)2 * BH * Sdim * Ddim];
__device__ bf16 g_pA_hi[(size_t)2 * Sdim * Kdim];      // [which][n][kk]
__device__ bf16 g_pA_lo[(size_t)2 * Sdim * Kdim];
__device__ bf16 g_kpT_hi[(size_t)BH * Ddim * Kdim];    // [bh][d][kk]
__device__ bf16 g_kpT_lo[(size_t)BH * Ddim * Kdim];
__device__ bf16 g_vp_hi[(size_t)BH * Kdim * Ddim];     // [bh][kk][d]
__device__ bf16 g_vp_lo[(size_t)BH * Kdim * Ddim];

// ---------------------------------------------------------------------------
// helpers
// ---------------------------------------------------------------------------
__device__ __forceinline__ uint32_t smem_u32(const void* p) {
    uint32_t a;
    asm("{ .reg .u64 t; cvta.to.shared.u64 t, %1; cvt.u32.u64 %0, t; }"
        : "=r"(a) : "l"(p));
    return a;
}
__device__ __forceinline__ void cpa16(uint32_t dst, const void* src) {
    asm volatile("cp.async.cg.shared.global [%0], [%1], 16;" :: "r"(dst), "l"(src));
}
#define CPA_COMMIT() asm volatile("cp.async.commit_group;" ::: "memory")
#define CPA_WAIT0()  asm volatile("cp.async.wait_group 0;" ::: "memory")
#define CPA_WAIT1()  asm volatile("cp.async.wait_group 1;" ::: "memory")

// split float -> bf16 hi + bf16 lo (lo = rn(x - hi))
__device__ __forceinline__ void splitbf(float x, bf16& h, bf16& l) {
    h = __float2bfloat16(x);
    l = __float2bfloat16(x - __bfloat162float(h));
}
// split a float4 into packed 4xbf16 hi and lo (uint2 each)
__device__ __forceinline__ void split4(float4 v, uint2& ho, uint2& lo) {
    bf16 h0, h1, h2, h3, l0, l1, l2, l3;
    splitbf(v.x, h0, l0); splitbf(v.y, h1, l1);
    splitbf(v.z, h2, l2); splitbf(v.w, h3, l3);
    __nv_bfloat162 hp0(h0, h1), hp1(h2, h3), lp0(l0, l1), lp1(l2, l3);
    ho.x = *(uint32_t*)&hp0; ho.y = *(uint32_t*)&hp1;
    lo.x = *(uint32_t*)&lp0; lo.y = *(uint32_t*)&lp1;
}

// ---------------------------------------------------------------------------
// Pre-pass: plain split (q, proj_k, proj_v)
// ---------------------------------------------------------------------------
__global__ __launch_bounds__(256) void split_plain(
    const float* __restrict__ src, bf16* __restrict__ hi, bf16* __restrict__ lo,
    size_t n4)
{
    for (size_t i = (size_t)blockIdx.x * 256 + threadIdx.x; i < n4;
         i += (size_t)gridDim.x * 256) {
        uint2 h, l;
        split4(((const float4*)src)[i], h, l);
        ((uint2*)hi)[i] = h;
        ((uint2*)lo)[i] = l;
    }
}

// Pre-pass: k/v with mask applied, split.
__global__ __launch_bounds__(256) void split_kv_kernel(
    const float* __restrict__ kin, const float* __restrict__ vin,
    const float* __restrict__ mask)
{
    const int which = blockIdx.y;
    const float* src = which ? vin : kin;
    bf16* hi = g_kv_hi + (size_t)which * BH * Sdim * Ddim;
    bf16* lo = g_kv_lo + (size_t)which * BH * Sdim * Ddim;
    const size_t n4 = (size_t)BH * Sdim * Ddim / 4;
    for (size_t i = (size_t)blockIdx.x * 256 + threadIdx.x; i < n4;
         i += (size_t)gridDim.x * 256) {
        float4 v = ((const float4*)src)[i];
        size_t e = i * 4;                        // bh*S*D + n*D + d
        size_t n = (e >> 6) & (Sdim - 1);
        size_t b = e >> 22;                      // / (Hdim*Sdim*Ddim)
        float m = mask[b * Sdim + n];
        v.x *= m; v.y *= m; v.z *= m; v.w *= m;
        uint2 h, l;
        split4(v, h, l);
        ((uint2*)hi)[i] = h;
        ((uint2*)lo)[i] = l;
    }
}

// ---------------------------------------------------------------------------
// Stage A: per (bh, which): C[kk=256, d=64] = sum_n proj[n,kk] * kv[n,d]
// 3x-bf16 WMMA (m16n16k16). Operands pre-split in gmem; pure cp.async staging,
// double buffered, 32-deep chunks. 256 threads / 8 warps; warp 64(kk) x 32(d).
// ---------------------------------------------------------------------------
#define PA_LDE 264                         // elements; row 528B
#define PB_LDE 72                          // row 144B
#define SA_B (32 * PA_LDE * 2)             // 16896
#define SB_B (32 * PB_LDE * 2)             // 4608
#define OFF_AH 0
#define OFF_AL (2 * SA_B)                  // 33792
#define OFF_BH (4 * SA_B)                  // 67584
#define OFF_BL (4 * SA_B + 2 * SB_B)       // 76800
#define PROJ_SMEM (4 * SA_B + 4 * SB_B)    // 86016
#define NCH (Sdim / 32)                    // 128

__global__ __launch_bounds__(256) void proj_gemm()
{
    extern __shared__ char smraw[];
    const uint32_t sb = smem_u32(smraw);
    const int bh = blockIdx.x, which = blockIdx.y;
    const int t = threadIdx.x, wid = t >> 5;
    const int m0 = (wid & 3) * 64;
    const int n0c = (wid >> 2) * 32;

    const char* Ah = (const char*)(g_pA_hi + (size_t)which * Sdim * Kdim);
    const char* Al = (const char*)(g_pA_lo + (size_t)which * Sdim * Kdim);
    const char* Bh = (const char*)(g_kv_hi + (size_t)(which * BH + bh) * Sdim * Ddim);
    const char* Bl = (const char*)(g_kv_lo + (size_t)(which * BH + bh) * Sdim * Ddim);

    wmma::fragment<wmma::accumulator, 16, 16, 16, float> acc[4][2];
#pragma unroll
    for (int mi = 0; mi < 4; mi++)
#pragma unroll
        for (int ni = 0; ni < 2; ni++) wmma::fill_fragment(acc[mi][ni], 0.0f);

    auto issue = [&](int ch, int buf) {
        const size_t aoff = (size_t)ch * 32 * 512;      // bytes: 32 rows x 512B
        const size_t boff = (size_t)ch * 32 * 128;      // 32 rows x 128B
#pragma unroll
        for (int l = 0; l < 4; l++) {                   // A: 1024 chunks/array
            int c = t + l * 256;
            int row = c >> 5, off = c & 31;
            cpa16(sb + OFF_AH + buf * SA_B + row * 528 + off * 16,
                  Ah + aoff + row * 512 + off * 16);
            cpa16(sb + OFF_AL + buf * SA_B + row * 528 + off * 16,
                  Al + aoff + row * 512 + off * 16);
        }
        {                                               // B: 256 chunks/array
            int row = t >> 3, off = t & 7;
            cpa16(sb + OFF_BH + buf * SB_B + row * 144 + off * 16,
                  Bh + boff + row * 128 + off * 16);
            cpa16(sb + OFF_BL + buf * SB_B + row * 144 + off * 16,
                  Bl + boff + row * 128 + off * 16);
        }
    };
    auto do_mma = [&](int buf) {
        const bf16* AH = (const bf16*)(smraw + OFF_AH + buf * SA_B);
        const bf16* AL = (const bf16*)(smraw + OFF_AL + buf * SA_B);
        const bf16* BHp = (const bf16*)(smraw + OFF_BH + buf * SB_B);
        const bf16* BLp = (const bf16*)(smraw + OFF_BL + buf * SB_B);
#pragma unroll
        for (int ks = 0; ks < 2; ks++) {
            wmma::fragment<wmma::matrix_b, 16, 16, 16, bf16, wmma::row_major> bh2[2], bl2[2];
#pragma unroll
            for (int ni = 0; ni < 2; ni++) {
                wmma::load_matrix_sync(bh2[ni], BHp + (ks * 16) * PB_LDE + n0c + ni * 16, PB_LDE);
                wmma::load_matrix_sync(bl2[ni], BLp + (ks * 16) * PB_LDE + n0c + ni * 16, PB_LDE);
            }
#pragma unroll
            for (int mi = 0; mi < 4; mi++) {
                wmma::fragment<wmma::matrix_a, 16, 16, 16, bf16, wmma::col_major> ah2, al2;
                wmma::load_matrix_sync(ah2, AH + (ks * 16) * PA_LDE + m0 + mi * 16, PA_LDE);
                wmma::load_matrix_sync(al2, AL + (ks * 16) * PA_LDE + m0 + mi * 16, PA_LDE);
#pragma unroll
                for (int ni = 0; ni < 2; ni++) {
                    wmma::mma_sync(acc[mi][ni], ah2, bl2[ni], acc[mi][ni]);
                    wmma::mma_sync(acc[mi][ni], al2, bh2[ni], acc[mi][ni]);
                    wmma::mma_sync(acc[mi][ni], ah2, bh2[ni], acc[mi][ni]);
                }
            }
        }
    };

    // prologue: two stages in flight
    issue(0, 0); CPA_COMMIT();
    issue(1, 1); CPA_COMMIT();

    for (int i = 0; i < NCH; i++) {
        const int cur = i & 1;
        if (i == NCH - 1) CPA_WAIT0(); else CPA_WAIT1();
        __syncthreads();
        do_mma(cur);
        if (i + 2 < NCH) {
            __syncthreads();
            issue(i + 2, cur);
            CPA_COMMIT();
        }
    }

    // ---- epilogue: stage fp32 [256][68], then split + layout-specific write
    __syncthreads();
    float* stage = (float*)smraw;                       // 69632 B <= 86016
#pragma unroll
    for (int mi = 0; mi < 4; mi++)
#pragma unroll
        for (int ni = 0; ni < 2; ni++)
            wmma::store_matrix_sync(stage + (size_t)(m0 + mi * 16) * 68 + n0c + ni * 16,
                                    acc[mi][ni], 68, wmma::mem_row_major);
    __syncthreads();

    if (which == 0) {
        bf16* dh = g_kpT_hi + (size_t)bh * Ddim * Kdim;  // [d][kk]
        bf16* dl = g_kpT_lo + (size_t)bh * Ddim * Kdim;
#pragma unroll
        for (int l = 0; l < 16; l++) {
            int v4i = t + l * 256;
            int d = v4i >> 6, kq = v4i & 63;
            float4 v;
            v.x = stage[(size_t)(kq * 4 + 0) * 68 + d];
            v.y = stage[(size_t)(kq * 4 + 1) * 68 + d];
            v.z = stage[(size_t)(kq * 4 + 2) * 68 + d];
            v.w = stage[(size_t)(kq * 4 + 3) * 68 + d];
            uint2 h, lo2;
            split4(v, h, lo2);
            *(uint2*)&dh[(size_t)d * Kdim + kq * 4] = h;
            *(uint2*)&dl[(size_t)d * Kdim + kq * 4] = lo2;
        }
    } else {
        bf16* dh = g_vp_hi + (size_t)bh * Kdim * Ddim;   // [kk][d]
        bf16* dl = g_vp_lo + (size_t)bh * Kdim * Ddim;
#pragma unroll
        for (int l = 0; l < 16; l++) {
            int v4i = t + l * 256;
            int kk = v4i >> 4, d4 = v4i & 15;
            float4 v = *(const float4*)&stage[(size_t)kk * 68 + d4 * 4];
            uint2 h, lo2;
            split4(v, h, lo2);
            *(uint2*)&dh[(size_t)kk * Ddim + d4 * 4] = h;
            *(uint2*)&dl[(size_t)kk * Ddim + d4 * 4] = lo2;
        }
    }
}

// ---------------------------------------------------------------------------
// Stage B: per (bh, 64-q tile), 512 threads / 16 warps, 3x-bf16 WMMA.
//  staging: {Q,KT} group0, V group1. P1 scores -> Sc(fp32). P2 softmax ->
//  Sc(fp32, for probs) + PH/PL (bf16, overlaying KT). P3 probs + out GEMM.
// ---------------------------------------------------------------------------
#define AQ_LDE 72
#define AK_LDE 264
#define ASC_LD 260
#define AV_LDE 72
#define AOFF_QH 0
#define AOFF_QL 9216
#define AOFF_KH 18432
#define AOFF_KL 52224
#define AOFF_PH AOFF_KH
#define AOFF_PL AOFF_KL
#define AOFF_SC 86016
#define AOFF_VH 152576
#define AOFF_VL 189440
#define ATTN_SMEM 226304

__global__ __launch_bounds__(512) void attn_wmma(
    float* __restrict__ out, float* __restrict__ probs)
{
    extern __shared__ char smraw[];
    const uint32_t sb = smem_u32(smraw);
    const int bh = blockIdx.y;
    const int q0 = blockIdx.x * 64;
    const int t = threadIdx.x, wid = t >> 5;

    // ---- async staging ----
    {
        const char* qh = (const char*)(g_q_hi + ((size_t)bh * Sdim + q0) * Ddim);
        const char* ql = (const char*)(g_q_lo + ((size_t)bh * Sdim + q0) * Ddim);
        {   // Q: 512 chunks per array (64 rows x 128B)
            int row = t >> 3, off = t & 7;
            cpa16(sb + AOFF_QH + row * 144 + off * 16, qh + row * 128 + off * 16);
            cpa16(sb + AOFF_QL + row * 144 + off * 16, ql + row * 128 + off * 16);
        }
        const char* kh = (const char*)(g_kpT_hi + (size_t)bh * Ddim * Kdim);
        const char* kl = (const char*)(g_kpT_lo + (size_t)bh * Ddim * Kdim);
#pragma unroll
        for (int l = 0; l < 4; l++) {   // KT: 2048 chunks per array (64 x 512B)
            int c = t + l * 512;
            int row = c >> 5, off = c & 31;
            cpa16(sb + AOFF_KH + row * 528 + off * 16, kh + row * 512 + off * 16);
            cpa16(sb + AOFF_KL + row * 528 + off * 16, kl + row * 512 + off * 16);
        }
        CPA_COMMIT();                   // group0: Q + KT
        const char* vh = (const char*)(g_vp_hi + (size_t)bh * Kdim * Ddim);
        const char* vl = (const char*)(g_vp_lo + (size_t)bh * Kdim * Ddim);
#pragma unroll
        for (int l = 0; l < 4; l++) {   // V: 2048 chunks per array (256 x 128B)
            int c = t + l * 512;
            int row = c >> 3, off = c & 7;
            cpa16(sb + AOFF_VH + row * 144 + off * 16, vh + row * 128 + off * 16);
            cpa16(sb + AOFF_VL + row * 144 + off * 16, vl + row * 128 + off * 16);
        }
        CPA_COMMIT();                   // group1: V
    }
    CPA_WAIT1();                        // Q + KT ready
    __syncthreads();

    float* Sc = (float*)(smraw + AOFF_SC);

    // ---- P1: scores = Q @ KT (3x-bf16); warp: M=64 x N=16 at n0=wid*16 ----
    {
        const int n0 = wid * 16;
        const bf16* QH = (const bf16*)(smraw + AOFF_QH);
        const bf16* QL = (const bf16*)(smraw + AOFF_QL);
        const bf16* KH = (const bf16*)(smraw + AOFF_KH);
        const bf16* KL = (const bf16*)(smraw + AOFF_KL);
        wmma::fragment<wmma::accumulator, 16, 16, 16, float> acc[4];
#pragma unroll
        for (int mi = 0; mi < 4; mi++) wmma::fill_fragment(acc[mi], 0.0f);
#pragma unroll
        for (int ks = 0; ks < 4; ks++) {
            const int d0 = ks * 16;
            wmma::fragment<wmma::matrix_b, 16, 16, 16, bf16, wmma::row_major> bh2, bl2;
            wmma::load_matrix_sync(bh2, KH + d0 * AK_LDE + n0, AK_LDE);
            wmma::load_matrix_sync(bl2, KL + d0 * AK_LDE + n0, AK_LDE);
#pragma unroll
            for (int mi = 0; mi < 4; mi++) {
                wmma::fragment<wmma::matrix_a, 16, 16, 16, bf16, wmma::row_major> ah2, al2;
                wmma::load_matrix_sync(ah2, QH + (mi * 16) * AQ_LDE + d0, AQ_LDE);
                wmma::load_matrix_sync(al2, QL + (mi * 16) * AQ_LDE + d0, AQ_LDE);
                wmma::mma_sync(acc[mi], ah2, bl2, acc[mi]);
                wmma::mma_sync(acc[mi], al2, bh2, acc[mi]);
                wmma::mma_sync(acc[mi], ah2, bh2, acc[mi]);
            }
        }
#pragma unroll
        for (int mi = 0; mi < 4; mi++) {
#pragma unroll
            for (int e = 0; e < acc[mi].num_elements; e++) acc[mi].x[e] *= 0.125f;
            wmma::store_matrix_sync(Sc + (mi * 16) * ASC_LD + n0, acc[mi],
                                    ASC_LD, wmma::mem_row_major);
        }
    }
    __syncthreads();

    // ---- P2: softmax. 8 lanes/row x 32 values. Writes Sc (fp32) + PH/PL ----
    {
        const int row = t >> 3;
        const int seg = t & 7;
        float v[32];
        float* base = Sc + row * ASC_LD + seg * 32;
#pragma unroll
        for (int j = 0; j < 8; j++) {
            float4 f = *(const float4*)&base[j * 4];
            v[j * 4] = f.x; v[j * 4 + 1] = f.y; v[j * 4 + 2] = f.z; v[j * 4 + 3] = f.w;
        }
        float mx = -1e30f;
#pragma unroll
        for (int i = 0; i < 32; i++) mx = fmaxf(mx, v[i]);
#pragma unroll
        for (int o = 1; o < 8; o <<= 1)
            mx = fmaxf(mx, __shfl_xor_sync(0xffffffffu, mx, o));
        float sum = 0.0f;
#pragma unroll
        for (int i = 0; i < 32; i++) { v[i] = __expf(v[i] - mx); sum += v[i]; }
#pragma unroll
        for (int o = 1; o < 8; o <<= 1)
            sum += __shfl_xor_sync(0xffffffffu, sum, o);
        float inv = __fdividef(1.0f, sum);

        bf16* PH = (bf16*)(smraw + AOFF_PH);
        bf16* PL = (bf16*)(smraw + AOFF_PL);
#pragma unroll
        for (int j = 0; j < 8; j++) {
            float4 p = make_float4(v[j * 4] * inv, v[j * 4 + 1] * inv,
                                   v[j * 4 + 2] * inv, v[j * 4 + 3] * inv);
            *(float4*)&base[j * 4] = p;
            uint2 h, l;
            split4(p, h, l);
            *(uint2*)&PH[(size_t)row * AK_LDE + seg * 32 + j * 4] = h;
            *(uint2*)&PL[(size_t)row * AK_LDE + seg * 32 + j * 4] = l;
        }
    }
    CPA_WAIT0();                        // V ready
    __syncthreads();

    // ---- P3a: probs -> gmem (fp32 from Sc, coalesced) ----
    if (probs) {
        float* pb = probs + ((size_t)bh * Sdim + q0) * Kdim;
#pragma unroll
        for (int l = 0; l < 8; l++) {
            int v4i = t + l * 512;                      // 4096 float4
            int row = v4i >> 6, c4 = v4i & 63;
            *(float4*)&pb[(size_t)row * Kdim + c4 * 4] =
                *(const float4*)&Sc[row * ASC_LD + c4 * 4];
        }
    }

    // ---- P3b: out = P @ V (3x-bf16); warp tile 16x16, 4x4 warp grid ----
    {
        const int m0 = (wid & 3) * 16;
        const int n0 = (wid >> 2) * 16;
        const bf16* PH = (const bf16*)(smraw + AOFF_PH);
        const bf16* PL = (const bf16*)(smraw + AOFF_PL);
        const bf16* VH = (const bf16*)(smraw + AOFF_VH);
        const bf16* VL = (const bf16*)(smraw + AOFF_VL);
        wmma::fragment<wmma::accumulator, 16, 16, 16, float> oacc;
        wmma::fill_fragment(oacc, 0.0f);
#pragma unroll 4
        for (int ks = 0; ks < 16; ks++) {
            const int k0 = ks * 16;
            wmma::fragment<wmma::matrix_a, 16, 16, 16, bf16, wmma::row_major> ah2, al2;
            wmma::fragment<wmma::matrix_b, 16, 16, 16, bf16, wmma::row_major> bh2, bl2;
            wmma::load_matrix_sync(ah2, PH + (size_t)m0 * AK_LDE + k0, AK_LDE);
            wmma::load_matrix_sync(al2, PL + (size_t)m0 * AK_LDE + k0, AK_LDE);
            wmma::load_matrix_sync(bh2, VH + (size_t)k0 * AV_LDE + n0, AV_LDE);
            wmma::load_matrix_sync(bl2, VL + (size_t)k0 * AV_LDE + n0, AV_LDE);
            wmma::mma_sync(oacc, ah2, bl2, oacc);
            wmma::mma_sync(oacc, al2, bh2, oacc);
            wmma::mma_sync(oacc, ah2, bh2, oacc);
        }
        float* ob = out + ((size_t)bh * Sdim + q0 + m0) * Ddim + n0;
        wmma::store_matrix_sync(ob, oacc, Ddim, wmma::mem_row_major);
    }
}

// ---------------------------------------------------------------------------
extern "C" void kernel_launch(void* const* d_in, const int* in_sizes, int n_in,
                              void* d_out, int out_size)
{
    const float* q    = (const float*)d_in[0];
    const float* k    = (const float*)d_in[1];
    const float* v    = (const float*)d_in[2];
    const float* mask = (const float*)d_in[3];
    const float* pk   = (const float*)d_in[4];
    const float* pv   = (const float*)d_in[5];

    float* out = (float*)d_out;
    const long OUT_ELEMS = (long)BH * Sdim * Ddim;   // 33,554,432
    float* probs = ((long)out_size > OUT_ELEMS) ? (out + OUT_ELEMS) : nullptr;

    cudaFuncSetAttribute(proj_gemm, cudaFuncAttributeMaxDynamicSharedMemorySize,
                         PROJ_SMEM);
    cudaFuncSetAttribute(attn_wmma, cudaFuncAttributeMaxDynamicSharedMemorySize,
                         ATTN_SMEM);

    bf16 *qhi, *qlo, *pAhi, *pAlo;
    cudaGetSymbolAddress((void**)&qhi, g_q_hi);
    cudaGetSymbolAddress((void**)&qlo, g_q_lo);
    cudaGetSymbolAddress((void**)&pAhi, g_pA_hi);
    cudaGetSymbolAddress((void**)&pAlo, g_pA_lo);

    const size_t qn4 = (size_t)BH * Sdim * Ddim / 4;
    const size_t pn4 = (size_t)Sdim * Kdim / 4;

    split_plain<<<4096, 256>>>(q, qhi, qlo, qn4);
    split_plain<<<512, 256>>>(pk, pAhi, pAlo, pn4);
    split_plain<<<512, 256>>>(pv, pAhi + (size_t)Sdim * Kdim,
                              pAlo + (size_t)Sdim * Kdim, pn4);
    split_kv_kernel<<<dim3(4096, 2), 256>>>(k, v, mask);

    proj_gemm<<<dim3(BH, 2), 256, PROJ_SMEM>>>();
    attn_wmma<<<dim3(Sdim / 64, BH), 512, ATTN_SMEM>>>(out, probs);
}

// round 13
// speedup vs baseline: 2.5234x; 1.1083x over previous
#include <cuda_runtime.h>
#include <mma.h>
#include <cuda_bf16.h>
#include <cstdint>

using namespace nvcuda;

#define Bdim 8
#define Hdim 16
#define Sdim 4096
#define Ddim 64
#define Kdim 256
#define BH (Bdim * Hdim)

typedef __nv_bfloat16 bf16;

// ---------------------------------------------------------------------------
// Scratch (no allocation; __device__ globals)
// ---------------------------------------------------------------------------
__device__ bf16 g_pA_hi[(size_t)2 * Sdim * Kdim];      // [which][n][kk]
__device__ bf16 g_pA_lo[(size_t)2 * Sdim * Kdim];
__device__ bf16 g_kpT_hi[(size_t)BH * Ddim * Kdim];    // [bh][d][kk]
__device__ bf16 g_kpT_lo[(size_t)BH * Ddim * Kdim];
__device__ bf16 g_vp_hi[(size_t)BH * Kdim * Ddim];     // [bh][kk][d]
__device__ bf16 g_vp_lo[(size_t)BH * Kdim * Ddim];

// ---------------------------------------------------------------------------
// helpers
// ---------------------------------------------------------------------------
__device__ __forceinline__ uint32_t smem_u32(const void* p) {
    uint32_t a;
    asm("{ .reg .u64 t; cvta.to.shared.u64 t, %1; cvt.u32.u64 %0, t; }"
        : "=r"(a) : "l"(p));
    return a;
}
__device__ __forceinline__ void cpa16(uint32_t dst, const void* src) {
    asm volatile("cp.async.cg.shared.global [%0], [%1], 16;" :: "r"(dst), "l"(src));
}
#define CPA_COMMIT() asm volatile("cp.async.commit_group;" ::: "memory")
#define CPA_WAIT0()  asm volatile("cp.async.wait_group 0;" ::: "memory")
#define CPA_WAIT1()  asm volatile("cp.async.wait_group 1;" ::: "memory")

// split float -> bf16 hi + bf16 lo (lo = rn(x - hi))
__device__ __forceinline__ void splitbf(float x, bf16& h, bf16& l) {
    h = __float2bfloat16(x);
    l = __float2bfloat16(x - __bfloat162float(h));
}
// split a float4 into packed 4xbf16 hi and lo (uint2 each)
__device__ __forceinline__ void split4(float4 v, uint2& ho, uint2& lo) {
    bf16 h0, h1, h2, h3, l0, l1, l2, l3;
    splitbf(v.x, h0, l0); splitbf(v.y, h1, l1);
    splitbf(v.z, h2, l2); splitbf(v.w, h3, l3);
    __nv_bfloat162 hp0(h0, h1), hp1(h2, h3), lp0(l0, l1), lp1(l2, l3);
    ho.x = *(uint32_t*)&hp0; ho.y = *(uint32_t*)&hp1;
    lo.x = *(uint32_t*)&lp0; lo.y = *(uint32_t*)&lp1;
}

// ---------------------------------------------------------------------------
// Pre-pass: split proj_k / proj_v (tiny: 2 x 4 MB)
// ---------------------------------------------------------------------------
__global__ __launch_bounds__(256) void split_plain(
    const float* __restrict__ src, bf16* __restrict__ hi, bf16* __restrict__ lo,
    size_t n4)
{
    for (size_t i = (size_t)blockIdx.x * 256 + threadIdx.x; i < n4;
         i += (size_t)gridDim.x * 256) {
        uint2 h, l;
        split4(((const float4*)src)[i], h, l);
        ((uint2*)hi)[i] = h;
        ((uint2*)lo)[i] = l;
    }
}

// ---------------------------------------------------------------------------
// Stage A: per (bh, which): C[kk=256, d=64] = sum_n proj[n,kk] * (kv[n,d]*m[n])
// 3x-bf16 WMMA (m16n16k16). A (pre-split) via cp.async double-buffer; B from
// fp32 gmem via LDG -> mask+split -> STS double-buffer (fused split_kv).
// 256 threads / 8 warps; warp tile 64(kk) x 32(d). One __syncthreads / chunk.
// ---------------------------------------------------------------------------
#define PA_LDE 264                         // elements; row 528B
#define PB_LDE 72                          // row 144B
#define SA_B (32 * PA_LDE * 2)             // 16896 (per hi-or-lo, per buffer)
#define SB_B (32 * PB_LDE * 2)             // 4608
#define OFF_AH 0
#define OFF_AL (2 * SA_B)                  // 33792
#define OFF_BH (4 * SA_B)                  // 67584
#define OFF_BL (4 * SA_B + 2 * SB_B)       // 76800
#define PROJ_SMEM (4 * SA_B + 4 * SB_B)    // 86016
#define NCH (Sdim / 32)                    // 128

__global__ __launch_bounds__(256) void proj_gemm(
    const float* __restrict__ kin, const float* __restrict__ vin,
    const float* __restrict__ mask)
{
    extern __shared__ char smraw[];
    const uint32_t sb = smem_u32(smraw);
    const int bh = blockIdx.x, which = blockIdx.y, b = bh >> 4;
    const int t = threadIdx.x, wid = t >> 5;
    const int m0 = (wid & 3) * 64;
    const int n0c = (wid >> 2) * 32;

    const char* Ah = (const char*)(g_pA_hi + (size_t)which * Sdim * Kdim);
    const char* Al = (const char*)(g_pA_lo + (size_t)which * Sdim * Kdim);
    const float* Bg = (which ? vin : kin) + (size_t)bh * Sdim * Ddim;  // [S][64]
    const float* mk = mask + (size_t)b * Sdim;

    wmma::fragment<wmma::accumulator, 16, 16, 16, float> acc[4][2];
#pragma unroll
    for (int mi = 0; mi < 4; mi++)
#pragma unroll
        for (int ni = 0; ni < 2; ni++) wmma::fill_fragment(acc[mi][ni], 0.0f);

    float4 br[2];
    float brm[2];

    auto issueA = [&](int ch, int buf) {
        const size_t aoff = (size_t)ch * 32 * 512;      // bytes: 32 rows x 512B
#pragma unroll
        for (int l = 0; l < 4; l++) {                   // 1024 chunks per array
            int c = t + l * 256;
            int row = c >> 5, off = c & 31;
            cpa16(sb + OFF_AH + buf * SA_B + row * 528 + off * 16,
                  Ah + aoff + row * 512 + off * 16);
            cpa16(sb + OFF_AL + buf * SA_B + row * 528 + off * 16,
                  Al + aoff + row * 512 + off * 16);
        }
    };
    auto ldgB = [&](int ch) {                           // 32 rows x 16 float4
#pragma unroll
        for (int l = 0; l < 2; l++) {
            int idx = t + l * 256;
            int row = idx >> 4, c4 = idx & 15;
            br[l]  = *(const float4*)&Bg[(size_t)(ch * 32 + row) * Ddim + c4 * 4];
            brm[l] = mk[ch * 32 + row];
        }
    };
    auto stsB = [&](int buf) {
        bf16* BHp = (bf16*)(smraw + OFF_BH + buf * SB_B);
        bf16* BLp = (bf16*)(smraw + OFF_BL + buf * SB_B);
#pragma unroll
        for (int l = 0; l < 2; l++) {
            int idx = t + l * 256;
            int row = idx >> 4, c4 = idx & 15;
            float4 v = br[l]; float m = brm[l];
            v.x *= m; v.y *= m; v.z *= m; v.w *= m;
            uint2 h, lo;
            split4(v, h, lo);
            *(uint2*)&BHp[row * PB_LDE + c4 * 4] = h;
            *(uint2*)&BLp[row * PB_LDE + c4 * 4] = lo;
        }
    };
    auto do_mma = [&](int buf) {
        const bf16* AH = (const bf16*)(smraw + OFF_AH + buf * SA_B);
        const bf16* AL = (const bf16*)(smraw + OFF_AL + buf * SA_B);
        const bf16* BHp = (const bf16*)(smraw + OFF_BH + buf * SB_B);
        const bf16* BLp = (const bf16*)(smraw + OFF_BL + buf * SB_B);
#pragma unroll
        for (int ks = 0; ks < 2; ks++) {
            wmma::fragment<wmma::matrix_b, 16, 16, 16, bf16, wmma::row_major> bh2[2], bl2[2];
#pragma unroll
            for (int ni = 0; ni < 2; ni++) {
                wmma::load_matrix_sync(bh2[ni], BHp + (ks * 16) * PB_LDE + n0c + ni * 16, PB_LDE);
                wmma::load_matrix_sync(bl2[ni], BLp + (ks * 16) * PB_LDE + n0c + ni * 16, PB_LDE);
            }
#pragma unroll
            for (int mi = 0; mi < 4; mi++) {
                wmma::fragment<wmma::matrix_a, 16, 16, 16, bf16, wmma::col_major> ah2, al2;
                wmma::load_matrix_sync(ah2, AH + (ks * 16) * PA_LDE + m0 + mi * 16, PA_LDE);
                wmma::load_matrix_sync(al2, AL + (ks * 16) * PA_LDE + m0 + mi * 16, PA_LDE);
#pragma unroll
                for (int ni = 0; ni < 2; ni++) {
                    wmma::mma_sync(acc[mi][ni], ah2, bl2[ni], acc[mi][ni]);
                    wmma::mma_sync(acc[mi][ni], al2, bh2[ni], acc[mi][ni]);
                    wmma::mma_sync(acc[mi][ni], ah2, bh2[ni], acc[mi][ni]);
                }
            }
        }
    };

    // ---- prologue ----
    ldgB(0);
    issueA(0, 0); CPA_COMMIT();
    CPA_WAIT0();
    stsB(0);
    ldgB(1);
    __syncthreads();

    // ---- mainloop: one sync per chunk (R9-validated structure) ----
    for (int i = 0; i < NCH; i++) {
        const int cur = i & 1, nxt = cur ^ 1;
        if (i + 1 < NCH) {
            issueA(i + 1, nxt);
            CPA_COMMIT();
            stsB(nxt);                    // br holds chunk i+1
        }
        if (i + 2 < NCH) ldgB(i + 2);
        do_mma(cur);
        if (i + 1 < NCH) CPA_WAIT0();
        __syncthreads();
    }

    // ---- epilogue: stage fp32 [256][68], then split + layout-specific write
    float* stage = (float*)smraw;                       // 69632 B <= 86016
#pragma unroll
    for (int mi = 0; mi < 4; mi++)
#pragma unroll
        for (int ni = 0; ni < 2; ni++)
            wmma::store_matrix_sync(stage + (size_t)(m0 + mi * 16) * 68 + n0c + ni * 16,
                                    acc[mi][ni], 68, wmma::mem_row_major);
    __syncthreads();

    if (which == 0) {
        bf16* dh = g_kpT_hi + (size_t)bh * Ddim * Kdim;  // [d][kk]
        bf16* dl = g_kpT_lo + (size_t)bh * Ddim * Kdim;
#pragma unroll
        for (int l = 0; l < 16; l++) {
            int v4i = t + l * 256;
            int d = v4i >> 6, kq = v4i & 63;
            float4 v;
            v.x = stage[(size_t)(kq * 4 + 0) * 68 + d];
            v.y = stage[(size_t)(kq * 4 + 1) * 68 + d];
            v.z = stage[(size_t)(kq * 4 + 2) * 68 + d];
            v.w = stage[(size_t)(kq * 4 + 3) * 68 + d];
            uint2 h, lo2;
            split4(v, h, lo2);
            *(uint2*)&dh[(size_t)d * Kdim + kq * 4] = h;
            *(uint2*)&dl[(size_t)d * Kdim + kq * 4] = lo2;
        }
    } else {
        bf16* dh = g_vp_hi + (size_t)bh * Kdim * Ddim;   // [kk][d]
        bf16* dl = g_vp_lo + (size_t)bh * Kdim * Ddim;
#pragma unroll
        for (int l = 0; l < 16; l++) {
            int v4i = t + l * 256;
            int kk = v4i >> 4, d4 = v4i & 15;
            float4 v = *(const float4*)&stage[(size_t)kk * 68 + d4 * 4];
            uint2 h, lo2;
            split4(v, h, lo2);
            *(uint2*)&dh[(size_t)kk * Ddim + d4 * 4] = h;
            *(uint2*)&dl[(size_t)kk * Ddim + d4 * 4] = lo2;
        }
    }
}

// ---------------------------------------------------------------------------
// Stage B: per (bh, 64-q tile), 512 threads / 16 warps, 3x-bf16 WMMA.
//  Q: fp32 LDG -> split -> STS (fused split_q). KT group0 + V group1 cp.async.
//  P1 scores -> Sc(fp32). P2 softmax -> Sc + PH/PL (overlaying KT).
//  P3: warps 0-7 out-GEMM (16x32 tiles) || warps 8-15 probs store.
// ---------------------------------------------------------------------------
#define AQ_LDE 72
#define AK_LDE 264
#define ASC_LD 260
#define AV_LDE 72
#define AOFF_QH 0
#define AOFF_QL 9216
#define AOFF_KH 18432
#define AOFF_KL 52224
#define AOFF_PH AOFF_KH
#define AOFF_PL AOFF_KL
#define AOFF_SC 86016
#define AOFF_VH 152576
#define AOFF_VL 189440
#define ATTN_SMEM 226304

__global__ __launch_bounds__(512) void attn_wmma(
    const float* __restrict__ q, float* __restrict__ out, float* __restrict__ probs)
{
    extern __shared__ char smraw[];
    const uint32_t sb = smem_u32(smraw);
    const int bh = blockIdx.y;
    const int q0 = blockIdx.x * 64;
    const int t = threadIdx.x, wid = t >> 5;

    // ---- async staging: KT group0, V group1 ----
    {
        const char* kh = (const char*)(g_kpT_hi + (size_t)bh * Ddim * Kdim);
        const char* kl = (const char*)(g_kpT_lo + (size_t)bh * Ddim * Kdim);
#pragma unroll
        for (int l = 0; l < 4; l++) {   // KT: 2048 chunks per array (64 x 512B)
            int c = t + l * 512;
            int row = c >> 5, off = c & 31;
            cpa16(sb + AOFF_KH + row * 528 + off * 16, kh + row * 512 + off * 16);
            cpa16(sb + AOFF_KL + row * 528 + off * 16, kl + row * 512 + off * 16);
        }
        CPA_COMMIT();                   // group0: KT
        const char* vh = (const char*)(g_vp_hi + (size_t)bh * Kdim * Ddim);
        const char* vl = (const char*)(g_vp_lo + (size_t)bh * Kdim * Ddim);
#pragma unroll
        for (int l = 0; l < 4; l++) {   // V: 2048 chunks per array (256 x 128B)
            int c = t + l * 512;
            int row = c >> 3, off = c & 7;
            cpa16(sb + AOFF_VH + row * 144 + off * 16, vh + row * 128 + off * 16);
            cpa16(sb + AOFF_VL + row * 144 + off * 16, vl + row * 128 + off * 16);
        }
        CPA_COMMIT();                   // group1: V
    }

    // ---- Q: fp32 LDG -> split -> STS (overlaps with cp.async in flight) ----
    {
        const float* qg = q + ((size_t)bh * Sdim + q0) * Ddim;
        bf16* QH = (bf16*)(smraw + AOFF_QH);
        bf16* QL = (bf16*)(smraw + AOFF_QL);
#pragma unroll
        for (int l = 0; l < 2; l++) {   // 1024 float4 = 64 rows x 16
            int idx = t + l * 512;
            int row = idx >> 4, c4 = idx & 15;
            float4 v = *(const float4*)&qg[(size_t)row * Ddim + c4 * 4];
            uint2 h, lo;
            split4(v, h, lo);
            *(uint2*)&QH[row * AQ_LDE + c4 * 4] = h;
            *(uint2*)&QL[row * AQ_LDE + c4 * 4] = lo;
        }
    }
    CPA_WAIT1();                        // KT ready (Q via STS, synced below)
    __syncthreads();

    float* Sc = (float*)(smraw + AOFF_SC);

    // ---- P1: scores = Q @ KT (3x-bf16); warp: M=64 x N=16 at n0=wid*16 ----
    {
        const int n0 = wid * 16;
        const bf16* QH = (const bf16*)(smraw + AOFF_QH);
        const bf16* QL = (const bf16*)(smraw + AOFF_QL);
        const bf16* KH = (const bf16*)(smraw + AOFF_KH);
        const bf16* KL = (const bf16*)(smraw + AOFF_KL);
        wmma::fragment<wmma::accumulator, 16, 16, 16, float> acc[4];
#pragma unroll
        for (int mi = 0; mi < 4; mi++) wmma::fill_fragment(acc[mi], 0.0f);
#pragma unroll
        for (int ks = 0; ks < 4; ks++) {
            const int d0 = ks * 16;
            wmma::fragment<wmma::matrix_b, 16, 16, 16, bf16, wmma::row_major> bh2, bl2;
            wmma::load_matrix_sync(bh2, KH + d0 * AK_LDE + n0, AK_LDE);
            wmma::load_matrix_sync(bl2, KL + d0 * AK_LDE + n0, AK_LDE);
#pragma unroll
            for (int mi = 0; mi < 4; mi++) {
                wmma::fragment<wmma::matrix_a, 16, 16, 16, bf16, wmma::row_major> ah2, al2;
                wmma::load_matrix_sync(ah2, QH + (mi * 16) * AQ_LDE + d0, AQ_LDE);
                wmma::load_matrix_sync(al2, QL + (mi * 16) * AQ_LDE + d0, AQ_LDE);
                wmma::mma_sync(acc[mi], ah2, bl2, acc[mi]);
                wmma::mma_sync(acc[mi], al2, bh2, acc[mi]);
                wmma::mma_sync(acc[mi], ah2, bh2, acc[mi]);
            }
        }
#pragma unroll
        for (int mi = 0; mi < 4; mi++) {
#pragma unroll
            for (int e = 0; e < acc[mi].num_elements; e++) acc[mi].x[e] *= 0.125f;
            wmma::store_matrix_sync(Sc + (mi * 16) * ASC_LD + n0, acc[mi],
                                    ASC_LD, wmma::mem_row_major);
        }
    }
    __syncthreads();

    // ---- P2: softmax. 8 lanes/row x 32 values. Writes Sc (fp32) + PH/PL ----
    {
        const int row = t >> 3;
        const int seg = t & 7;
        float v[32];
        float* base = Sc + row * ASC_LD + seg * 32;
#pragma unroll
        for (int j = 0; j < 8; j++) {
            float4 f = *(const float4*)&base[j * 4];
            v[j * 4] = f.x; v[j * 4 + 1] = f.y; v[j * 4 + 2] = f.z; v[j * 4 + 3] = f.w;
        }
        float mx = -1e30f;
#pragma unroll
        for (int i = 0; i < 32; i++) mx = fmaxf(mx, v[i]);
#pragma unroll
        for (int o = 1; o < 8; o <<= 1)
            mx = fmaxf(mx, __shfl_xor_sync(0xffffffffu, mx, o));
        float sum = 0.0f;
#pragma unroll
        for (int i = 0; i < 32; i++) { v[i] = __expf(v[i] - mx); sum += v[i]; }
#pragma unroll
        for (int o = 1; o < 8; o <<= 1)
            sum += __shfl_xor_sync(0xffffffffu, sum, o);
        float inv = __fdividef(1.0f, sum);

        bf16* PH = (bf16*)(smraw + AOFF_PH);
        bf16* PL = (bf16*)(smraw + AOFF_PL);
#pragma unroll
        for (int j = 0; j < 8; j++) {
            float4 p = make_float4(v[j * 4] * inv, v[j * 4 + 1] * inv,
                                   v[j * 4 + 2] * inv, v[j * 4 + 3] * inv);
            *(float4*)&base[j * 4] = p;
            uint2 h, l;
            split4(p, h, l);
            *(uint2*)&PH[(size_t)row * AK_LDE + seg * 32 + j * 4] = h;
            *(uint2*)&PL[(size_t)row * AK_LDE + seg * 32 + j * 4] = l;
        }
    }
    CPA_WAIT0();                        // V ready
    __syncthreads();

    // ---- P3: warps 0-7 out-GEMM || warps 8-15 probs store ----
    if (wid < 8) {
        const int m0 = (wid & 3) * 16;
        const int n0 = (wid >> 2) * 32;
        const bf16* PH = (const bf16*)(smraw + AOFF_PH);
        const bf16* PL = (const bf16*)(smraw + AOFF_PL);
        const bf16* VH = (const bf16*)(smraw + AOFF_VH);
        const bf16* VL = (const bf16*)(smraw + AOFF_VL);
        wmma::fragment<wmma::accumulator, 16, 16, 16, float> oacc[2];
#pragma unroll
        for (int ni = 0; ni < 2; ni++) wmma::fill_fragment(oacc[ni], 0.0f);
#pragma unroll 4
        for (int ks = 0; ks < 16; ks++) {
            const int k0 = ks * 16;
            wmma::fragment<wmma::matrix_a, 16, 16, 16, bf16, wmma::row_major> ah2, al2;
            wmma::load_matrix_sync(ah2, PH + (size_t)m0 * AK_LDE + k0, AK_LDE);
            wmma::load_matrix_sync(al2, PL + (size_t)m0 * AK_LDE + k0, AK_LDE);
#pragma unroll
            for (int ni = 0; ni < 2; ni++) {
                wmma::fragment<wmma::matrix_b, 16, 16, 16, bf16, wmma::row_major> bh2, bl2;
                wmma::load_matrix_sync(bh2, VH + (size_t)k0 * AV_LDE + n0 + ni * 16, AV_LDE);
                wmma::load_matrix_sync(bl2, VL + (size_t)k0 * AV_LDE + n0 + ni * 16, AV_LDE);
                wmma::mma_sync(oacc[ni], ah2, bl2, oacc[ni]);
                wmma::mma_sync(oacc[ni], al2, bh2, oacc[ni]);
                wmma::mma_sync(oacc[ni], ah2, bh2, oacc[ni]);
            }
        }
        float* ob = out + ((size_t)bh * Sdim + q0 + m0) * Ddim + n0;
#pragma unroll
        for (int ni = 0; ni < 2; ni++)
            wmma::store_matrix_sync(ob + ni * 16, oacc[ni], Ddim,
                                    wmma::mem_row_major);
    } else if (probs) {
        float* pb = probs + ((size_t)bh * Sdim + q0) * Kdim;
        const int j = t - 256;          // 0..255
#pragma unroll
        for (int l = 0; l < 16; l++) {
            int v4i = j + l * 256;                      // 4096 float4
            int row = v4i >> 6, c4 = v4i & 63;
            *(float4*)&pb[(size_t)row * Kdim + c4 * 4] =
                *(const float4*)&Sc[row * ASC_LD + c4 * 4];
        }
    }
}

// ---------------------------------------------------------------------------
extern "C" void kernel_launch(void* const* d_in, const int* in_sizes, int n_in,
                              void* d_out, int out_size)
{
    const float* q    = (const float*)d_in[0];
    const float* k    = (const float*)d_in[1];
    const float* v    = (const float*)d_in[2];
    const float* mask = (const float*)d_in[3];
    const float* pk   = (const float*)d_in[4];
    const float* pv   = (const float*)d_in[5];

    float* out = (float*)d_out;
    const long OUT_ELEMS = (long)BH * Sdim * Ddim;   // 33,554,432
    float* probs = ((long)out_size > OUT_ELEMS) ? (out + OUT_ELEMS) : nullptr;

    cudaFuncSetAttribute(proj_gemm, cudaFuncAttributeMaxDynamicSharedMemorySize,
                         PROJ_SMEM);
    cudaFuncSetAttribute(attn_wmma, cudaFuncAttributeMaxDynamicSharedMemorySize,
                         ATTN_SMEM);

    bf16 *pAhi, *pAlo;
    cudaGetSymbolAddress((void**)&pAhi, g_pA_hi);
    cudaGetSymbolAddress((void**)&pAlo, g_pA_lo);
    const size_t pn4 = (size_t)Sdim * Kdim / 4;

    split_plain<<<512, 256>>>(pk, pAhi, pAlo, pn4);
    split_plain<<<512, 256>>>(pv, pAhi + (size_t)Sdim * Kdim,
                              pAlo + (size_t)Sdim * Kdim, pn4);

    proj_gemm<<<dim3(BH, 2), 256, PROJ_SMEM>>>(k, v, mask);
    attn_wmma<<<dim3(Sdim / 64, BH), 512, ATTN_SMEM>>>(q, out, probs);
}